// round 13
// baseline (speedup 1.0000x reference)
#include <cuda_runtime.h>

// CenterLoss collapses algebraically: after masking, only the true-label
// column survives; the other C-1 zeros clamp to 1e-12 each.
//   loss = sum_n clamp(||x_n - c_{lab_n}||^2, 1e-12, 1e12) + N*(C-1)*1e-12
//
// R13: kill the MEMBAR. Every fused variant (8.2us) contained
// __threadfence() in each CTA's tail; the tail-less R2 gather implied ~4us
// cheaper. Replace store+fence+atomic with:
//   red.relaxed.gpu.add.u64  (fixed-point 2^24 partial, order-independent)
//   atom.acq_rel.gpu.add.u32 (counter; release orders the red before it)
// Last CTA: acq_rel synchronizes-with all releases -> one ld.acquire of the
// accumulator. No MEMBAR anywhere. Deterministic (integer accumulation).
// Body: proven config, 1024 CTAs x 256 thr, half-row/warp, LDG.256.

#define N_ROWS 4096      // 16 * 256
#define FEAT_DIM 512
#define NUM_CLASSES 10000
#define NUM_CTAS 1024
#define ROWS_PER_CTA 4
#define FP_SCALE 16777216.0         // 2^24

__device__ unsigned long long g_acc = 0ull;
__device__ unsigned int g_done_count = 0;

struct f8 { float v[8]; };

__device__ __forceinline__ f8 ldg256(const float* p)
{
    f8 r;
    asm volatile(
        "ld.global.nc.L2::evict_last.v8.b32 "
        "{%0,%1,%2,%3,%4,%5,%6,%7}, [%8];"
        : "=f"(r.v[0]), "=f"(r.v[1]), "=f"(r.v[2]), "=f"(r.v[3]),
          "=f"(r.v[4]), "=f"(r.v[5]), "=f"(r.v[6]), "=f"(r.v[7])
        : "l"(p));
    return r;
}

__global__ __launch_bounds__(256, 8) void center_loss_kernel(
    const float* __restrict__ x,
    const int* __restrict__ labels,
    const float* __restrict__ centers,
    float* __restrict__ out)
{
    const int t = threadIdx.x;
    const int warp = t >> 5;          // 0..7
    const int lane = t & 31;
    const int cta = blockIdx.x;
    const int lrow = warp >> 1;       // 0..3 local row
    const int half = warp & 1;        // half of the row

    const int row = cta * ROWS_PER_CTA + lrow;

    __shared__ float s_half[8];

    // Label first (head of the dependent chain), per-warp, no barrier.
    int c = 0;
    if (lane == 0) c = labels[row];

    // x load (one LDG.256 per lane) flies during the label latency.
    const float* xr = x + (size_t)row * FEAT_DIM + half * 256 + lane * 8;
    f8 a = ldg256(xr);

    c = __shfl_sync(0xffffffffu, c, 0);
    c = min(max(c, 0), NUM_CLASSES - 1);

    const float* crp = centers + (size_t)c * FEAT_DIM + half * 256 + lane * 8;
    f8 b = ldg256(crp);

    float s = 0.0f;
    #pragma unroll
    for (int i = 0; i < 8; i++) {
        float d = a.v[i] - b.v[i];
        s += d * d;
    }

    // warp reduce -> lane 0 holds half-row sum
    #pragma unroll
    for (int o = 16; o > 0; o >>= 1)
        s += __shfl_xor_sync(0xffffffffu, s, o);

    if (lane == 0) s_half[warp] = s;
    __syncthreads();

    if (t == 0) {
        float acc = 0.0f;
        #pragma unroll
        for (int r = 0; r < ROWS_PER_CTA; r++) {
            float rs = s_half[2 * r] + s_half[2 * r + 1];
            rs = fminf(fmaxf(rs, 1e-12f), 1e12f);   // per-row clamp
            acc += rs;
        }

        // Order-independent fixed-point contribution (no fence needed).
        unsigned long long v =
            (unsigned long long)(long long)((double)acc * FP_SCALE);
        asm volatile("red.relaxed.gpu.global.add.u64 [%0], %1;"
                     :: "l"(&g_acc), "l"(v) : "memory");

        // Release: orders the red above before the counter increment.
        unsigned int done;
        asm volatile("atom.acq_rel.gpu.global.add.u32 %0, [%1], 1;"
                     : "=r"(done) : "l"(&g_done_count) : "memory");

        if (done == (unsigned int)(NUM_CTAS - 1)) {
            // acq_rel read of the final count synchronizes-with all
            // releasing CTAs -> their reds are visible.
            unsigned long long total;
            asm volatile("ld.acquire.gpu.global.u64 %0, [%1];"
                         : "=l"(total) : "l"(&g_acc) : "memory");
            const double zero_clamp_sum =
                (double)N_ROWS * (double)(NUM_CLASSES - 1) * 1e-12;
            out[0] = (float)((double)(long long)total / FP_SCALE
                             + zero_clamp_sum);
            // reset for next graph replay (no later readers this launch)
            asm volatile("st.relaxed.gpu.global.u64 [%0], 0;"
                         :: "l"(&g_acc) : "memory");
            asm volatile("st.relaxed.gpu.global.u32 [%0], 0;"
                         :: "l"(&g_done_count) : "memory");
        }
    }
}

extern "C" void kernel_launch(void* const* d_in, const int* in_sizes, int n_in,
                              void* d_out, int out_size)
{
    const float* x       = (const float*)d_in[0];  // (16,256,512) f32
    const int*   labels  = (const int*)d_in[1];    // (16,256) int32
    const float* centers = (const float*)d_in[2];  // (10000,512) f32
    float*       out     = (float*)d_out;          // scalar

    (void)in_sizes; (void)n_in; (void)out_size;

    center_loss_kernel<<<NUM_CTAS, 256>>>(x, labels, centers, out);
}

// round 14
// speedup vs baseline: 1.0115x; 1.0115x over previous
#include <cuda_runtime.h>

// CenterLoss collapses algebraically: after masking, only the true-label
// column survives; the other C-1 zeros clamp to 1e-12 each.
//   loss = sum_n clamp(||x_n - c_{lab_n}||^2, 1e-12, 1e12) + N*(C-1)*1e-12
//
// FINAL (lock-in of the best-measured config, R8):
// Ten structural variants (R4-R13: occupancy, MLP, load width, atomic count,
// tail depth, fences, L2 pinning) all pinned at 1.80-1.89 TB/s with dur =
// compulsory 15.3 MB / delivered BW ~= 8.2us. Traffic is minimal (x is
// compulsory; distinct centers read once, L2 serves duplicates) and the
// delivered BW is environment-fixed (parked DVFS for an isolated ~8us
// kernel). This is the floor; locking the fastest-measured variant:
//  - 1024 CTAs x 256 threads, half-row per warp
//  - per-warp label fetch overlapped with x loads (no pre-barrier)
//  - float2 (LDG.64) data loads, 8 per lane
//  - fused last-CTA fixed-order tail -> bitwise deterministic

#define N_ROWS 4096      // 16 * 256
#define FEAT_DIM 512
#define F2_PER_ROW (FEAT_DIM / 2)   // 256
#define NUM_CLASSES 10000
#define NUM_CTAS 1024
#define ROWS_PER_CTA 4

__device__ float g_cta_partials[NUM_CTAS];
__device__ unsigned int g_done_count = 0;

__global__ __launch_bounds__(256, 8) void center_loss_kernel(
    const float* __restrict__ x,
    const int* __restrict__ labels,
    const float* __restrict__ centers,
    float* __restrict__ out)
{
    const int t = threadIdx.x;
    const int warp = t >> 5;          // 0..7
    const int lane = t & 31;
    const int cta = blockIdx.x;
    const int lrow = warp >> 1;       // 0..3 local row
    const int half = warp & 1;        // half of the row

    const int row = cta * ROWS_PER_CTA + lrow;

    __shared__ float s_half[8];
    __shared__ bool s_is_last;

    // Label first (head of the dependent chain), per-warp, no barrier.
    int c = 0;
    if (lane == 0) c = labels[row];

    // x loads (LDG.64): independent, overlap the label latency.
    const float2* __restrict__ xr =
        reinterpret_cast<const float2*>(x) + (size_t)row * F2_PER_ROW + half * 128;
    float2 a0 = xr[lane];
    float2 a1 = xr[32 + lane];
    float2 a2 = xr[64 + lane];
    float2 a3 = xr[96 + lane];

    // Broadcast label, then the dependent center gather.
    c = __shfl_sync(0xffffffffu, c, 0);
    c = min(max(c, 0), NUM_CLASSES - 1);

    const float2* __restrict__ cr =
        reinterpret_cast<const float2*>(centers) + (size_t)c * F2_PER_ROW + half * 128;
    float2 b0 = cr[lane];
    float2 b1 = cr[32 + lane];
    float2 b2 = cr[64 + lane];
    float2 b3 = cr[96 + lane];

    float d0, d1;
    d0 = a0.x - b0.x; d1 = a0.y - b0.y;
    float s = d0 * d0 + d1 * d1;
    d0 = a1.x - b1.x; d1 = a1.y - b1.y;
    s += d0 * d0 + d1 * d1;
    d0 = a2.x - b2.x; d1 = a2.y - b2.y;
    s += d0 * d0 + d1 * d1;
    d0 = a3.x - b3.x; d1 = a3.y - b3.y;
    s += d0 * d0 + d1 * d1;

    // warp reduce -> lane 0 holds half-row sum
    #pragma unroll
    for (int o = 16; o > 0; o >>= 1)
        s += __shfl_xor_sync(0xffffffffu, s, o);

    if (lane == 0) s_half[warp] = s;
    __syncthreads();

    if (t == 0) {
        float acc = 0.0f;
        #pragma unroll
        for (int r = 0; r < ROWS_PER_CTA; r++) {
            float rs = s_half[2 * r] + s_half[2 * r + 1];
            rs = fminf(fmaxf(rs, 1e-12f), 1e12f);   // per-row clamp
            acc += rs;
        }
        g_cta_partials[cta] = acc;
        __threadfence();
        unsigned int v = atomicAdd(&g_done_count, 1u);
        s_is_last = (v == (unsigned int)(NUM_CTAS - 1));
    }
    __syncthreads();

    if (s_is_last) {
        // 1024 partials as 256 float4: one vector load per thread.
        float4 p = reinterpret_cast<const float4*>(g_cta_partials)[t];
        float v = (p.x + p.y) + (p.z + p.w);

        #pragma unroll
        for (int o = 16; o > 0; o >>= 1)
            v += __shfl_xor_sync(0xffffffffu, v, o);

        __shared__ float fs[8];
        if (lane == 0) fs[warp] = v;
        __syncthreads();

        if (t == 0) {
            const float zero_clamp_sum =
                (float)((double)N_ROWS * (double)(NUM_CLASSES - 1) * 1e-12);
            float r = 0.0f;
            #pragma unroll
            for (int w = 0; w < 8; w++) r += fs[w];
            out[0] = r + zero_clamp_sum;
            g_done_count = 0;   // reset for next graph replay
        }
    }
}

extern "C" void kernel_launch(void* const* d_in, const int* in_sizes, int n_in,
                              void* d_out, int out_size)
{
    const float* x       = (const float*)d_in[0];  // (16,256,512) f32
    const int*   labels  = (const int*)d_in[1];    // (16,256) int32
    const float* centers = (const float*)d_in[2];  // (10000,512) f32
    float*       out     = (float*)d_out;          // scalar

    (void)in_sizes; (void)n_in; (void)out_size;

    center_loss_kernel<<<NUM_CTAS, 256>>>(x, labels, centers, out);
}